// round 5
// baseline (speedup 1.0000x reference)
#include <cuda_runtime.h>

#define RB 64
#define CB 64
#define NROWS 8192
#define TCOLS 8192
#define T4 (TCOLS / 4)        // 2048 float4 per row
#define NCHUNK 8              // 1024 columns (256 float4) per chunk
#define NSPLIT 2              // row halves per row-block
#define NPART (NCHUNK * NSPLIT)
#define NBLK (NCHUNK * RB * NSPLIT)   // 1024 k_sum blocks

__device__ int   g_row_start[RB + 1];
__device__ int   g_col_start[CB + 1];
__device__ float g_partial[RB][NPART][CB];
__device__ int   g_done;

// ---------------------------------------------------------------------------
// Kernel 1: ids are SORTED with every block non-empty, so block b starts at
// the unique j with ids[j-1] != ids[j] == b. One parallel pass, no dependent
// chains. Block 0 handles rows, block 1 handles cols (run concurrently).
//   out[0..4095]      propensity (float32, written by k_sum's last block)
//   out[4096..4160]   row_cumsum (65, stored as float values)
//   out[4161..4225]   col_cumsum (65, stored as float values)
// Also resets g_done for the k_sum completion counter.
// ---------------------------------------------------------------------------
__global__ __launch_bounds__(1024) void k_bounds(const int* __restrict__ row_ids,
                                                 const int* __restrict__ col_ids,
                                                 float* __restrict__ out) {
    const int* __restrict__ ids = (blockIdx.x == 0) ? row_ids : col_ids;
    int* __restrict__ gstart = (blockIdx.x == 0) ? g_row_start : g_col_start;
    float* __restrict__ obase = out + RB * CB + blockIdx.x * 65;
    int tid = threadIdx.x;

    if (tid == 0) {
        gstart[0] = 0;       obase[0]  = 0.f;
        gstart[RB] = NROWS;  obase[RB] = (float)NROWS;
        if (blockIdx.x == 0) g_done = 0;
    }

    const int4* __restrict__ p = (const int4*)ids;
    for (int i = tid; i < NROWS / 4; i += 1024) {
        int4 v = p[i];
        int j = 4 * i;
        if (j > 0) {
            int prev = ids[j - 1];
            if (v.x != prev) { gstart[v.x] = j;     obase[v.x] = (float)j; }
        }
        if (v.y != v.x) { gstart[v.y] = j + 1; obase[v.y] = (float)(j + 1); }
        if (v.z != v.y) { gstart[v.z] = j + 2; obase[v.z] = (float)(j + 2); }
        if (v.w != v.z) { gstart[v.w] = j + 3; obase[v.w] = (float)(j + 3); }
    }
}

// ---------------------------------------------------------------------------
// Kernel 2: streaming column-strip reduction + fused epilogue.
// Block = (chunk, rb, half). Thread owns one float4 column group; sums down
// the rows of its half of row-block rb. Fully coalesced LDG.128 stream.
// Per-column sums collapse into shared acc[CB], deterministic partial per
// block. The LAST block to finish (atomic counter) folds all partials and
// runs the 1->3->3->1 relu MLP + sigmoid — no third kernel launch.
// ---------------------------------------------------------------------------
__global__ __launch_bounds__(256) void k_sum(const float* __restrict__ X,
                                             const int* __restrict__ col_ids,
                                             const float* __restrict__ W1,
                                             const float* __restrict__ b1,
                                             const float* __restrict__ W2,
                                             const float* __restrict__ b2,
                                             const float* __restrict__ W3,
                                             const float* __restrict__ b3,
                                             float* __restrict__ out) {
    int chunk = blockIdx.x;            // 0..NCHUNK-1
    int rb    = blockIdx.y;            // 0..RB-1
    int half  = blockIdx.z;            // 0..NSPLIT-1
    int r0 = g_row_start[rb];
    int r1 = g_row_start[rb + 1];
    int len = r1 - r0;
    int h0 = r0 + (len * half) / NSPLIT;
    int h1 = r0 + (len * (half + 1)) / NSPLIT;

    int c4 = chunk * 256 + threadIdx.x;          // float4 column index
    const float4* __restrict__ Xp = (const float4*)X;

    float ax = 0.f, ay = 0.f, az = 0.f, aw = 0.f;
    int base = h0 * T4 + c4;
    int n = h0;
    for (; n + 4 <= h1; n += 4, base += 4 * T4) {
        float4 v0 = Xp[base];
        float4 v1 = Xp[base + T4];
        float4 v2 = Xp[base + 2 * T4];
        float4 v3 = Xp[base + 3 * T4];
        ax += v0.x + v1.x + v2.x + v3.x;
        ay += v0.y + v1.y + v2.y + v3.y;
        az += v0.z + v1.z + v2.z + v3.z;
        aw += v0.w + v1.w + v2.w + v3.w;
    }
    for (; n < h1; n++, base += T4) {
        float4 v = Xp[base];
        ax += v.x; ay += v.y; az += v.z; aw += v.w;
    }

    __shared__ float sacc[CB];
    if (threadIdx.x < CB) sacc[threadIdx.x] = 0.f;
    __syncthreads();

    int t = c4 * 4;
    int cb0 = col_ids[t];
    int cb3 = col_ids[t + 3];
    if (cb0 == cb3) {
        atomicAdd(&sacc[cb0], ax + ay + az + aw);
    } else {
        int cb1 = col_ids[t + 1];
        int cb2 = col_ids[t + 2];
        atomicAdd(&sacc[cb0], ax);
        atomicAdd(&sacc[cb1], ay);
        atomicAdd(&sacc[cb2], az);
        atomicAdd(&sacc[cb3], aw);
    }
    __syncthreads();
    if (threadIdx.x < CB)
        g_partial[rb][chunk * NSPLIT + half][threadIdx.x] = sacc[threadIdx.x];

    // ---- completion-count epilogue: last block runs the MLP ----
    __shared__ int is_last;
    __threadfence();
    if (threadIdx.x == 0) {
        int c = atomicAdd(&g_done, 1);
        is_last = (c == NBLK - 1);
    }
    __syncthreads();
    if (!is_last) return;
    __threadfence();   // acquire all partials

    for (int idx = threadIdx.x; idx < RB * CB; idx += 256) {
        int prb = idx / CB;
        int pcb = idx % CB;
        float s = 0.f;
#pragma unroll
        for (int j = 0; j < NPART; j++) s += g_partial[prb][j][pcb];
        float rcnt = (float)(g_row_start[prb + 1] - g_row_start[prb]);
        float ccnt = (float)(g_col_start[pcb + 1] - g_col_start[pcb]);
        float x = s / (rcnt * ccnt);

        float h1v[3], h2v[3];
#pragma unroll
        for (int j = 0; j < 3; j++) h1v[j] = fmaxf(x * W1[j] + b1[j], 0.f);
#pragma unroll
        for (int j = 0; j < 3; j++) {
            float v = b2[j];
#pragma unroll
            for (int i = 0; i < 3; i++) v += h1v[i] * W2[i * 3 + j];
            h2v[j] = fmaxf(v, 0.f);
        }
        float o = b3[0];
#pragma unroll
        for (int i = 0; i < 3; i++) o += h2v[i] * W3[i];
        out[idx] = 1.f / (1.f + __expf(-o));
    }
}

extern "C" void kernel_launch(void* const* d_in, const int* in_sizes, int n_in,
                              void* d_out, int out_size) {
    const float* X       = (const float*)d_in[0];
    const int*   row_ids = (const int*)d_in[1];
    const int*   col_ids = (const int*)d_in[2];
    const float* W1      = (const float*)d_in[3];
    const float* b1      = (const float*)d_in[4];
    const float* W2      = (const float*)d_in[5];
    const float* b2      = (const float*)d_in[6];
    const float* W3      = (const float*)d_in[7];
    const float* b3      = (const float*)d_in[8];
    float* out = (float*)d_out;

    k_bounds<<<2, 1024>>>(row_ids, col_ids, out);
    k_sum<<<dim3(NCHUNK, RB, NSPLIT), 256>>>(X, col_ids,
                                             W1, b1, W2, b2, W3, b3, out);
}

// round 6
// speedup vs baseline: 1.3328x; 1.3328x over previous
#include <cuda_runtime.h>

#define RB 64
#define CB 64
#define NROWS 8192
#define TCOLS 8192
#define T4 (TCOLS / 4)        // 2048 float4 per row
#define NCHUNK 8              // 1024 columns (256 float4) per chunk
#define NSPLIT 2              // row halves per row-block
#define NPART (NCHUNK * NSPLIT)

__device__ int   g_row_start[RB + 1];
__device__ int   g_col_start[CB + 1];
__device__ float g_partial[RB][NPART][CB];

// ---------------------------------------------------------------------------
// Kernel 1: ids are SORTED with every block non-empty, so block b starts at
// the unique j with ids[j-1] != ids[j] == b. One parallel pass, no dependent
// chains. Block 0 handles rows, block 1 handles cols (concurrent SMs).
//   out[0..4095]      propensity (float32, written by k_mlp)
//   out[4096..4160]   row_cumsum (65, stored as float values)
//   out[4161..4225]   col_cumsum (65, stored as float values)
// ---------------------------------------------------------------------------
__global__ __launch_bounds__(1024) void k_bounds(const int* __restrict__ row_ids,
                                                 const int* __restrict__ col_ids,
                                                 float* __restrict__ out) {
    const int* __restrict__ ids = (blockIdx.x == 0) ? row_ids : col_ids;
    int* __restrict__ gstart = (blockIdx.x == 0) ? g_row_start : g_col_start;
    float* __restrict__ obase = out + RB * CB + blockIdx.x * 65;
    int tid = threadIdx.x;

    if (tid == 0) {
        gstart[0] = 0;       obase[0]  = 0.f;
        gstart[RB] = NROWS;  obase[RB] = (float)NROWS;
    }

    const int4* __restrict__ p = (const int4*)ids;
    for (int i = tid; i < NROWS / 4; i += 1024) {
        int4 v = p[i];
        int j = 4 * i;
        if (j > 0) {
            int prev = ids[j - 1];
            if (v.x != prev) { gstart[v.x] = j;     obase[v.x] = (float)j; }
        }
        if (v.y != v.x) { gstart[v.y] = j + 1; obase[v.y] = (float)(j + 1); }
        if (v.z != v.y) { gstart[v.z] = j + 2; obase[v.z] = (float)(j + 2); }
        if (v.w != v.z) { gstart[v.w] = j + 3; obase[v.w] = (float)(j + 3); }
    }
}

// ---------------------------------------------------------------------------
// Kernel 2: streaming column-strip reduction.
// Block = (chunk, rb, half). Thread owns one float4 column group; sums down
// the rows of its half of row-block rb. Unroll-8: 8 independent LDG.128 per
// iteration (MLP_p1=8) + pairwise add tree. Per-column sums collapse into
// shared acc[CB]; deterministic partial per block. No fences, no fusion.
// ---------------------------------------------------------------------------
__global__ __launch_bounds__(256) void k_sum(const float* __restrict__ X,
                                             const int* __restrict__ col_ids) {
    int chunk = blockIdx.x;            // 0..NCHUNK-1
    int rb    = blockIdx.y;            // 0..RB-1
    int half  = blockIdx.z;            // 0..NSPLIT-1
    int r0 = g_row_start[rb];
    int r1 = g_row_start[rb + 1];
    int len = r1 - r0;
    int h0 = r0 + (len * half) / NSPLIT;
    int h1 = r0 + (len * (half + 1)) / NSPLIT;

    int c4 = chunk * 256 + threadIdx.x;          // float4 column index
    const float4* __restrict__ Xp = (const float4*)X;

    float ax = 0.f, ay = 0.f, az = 0.f, aw = 0.f;
    int base = h0 * T4 + c4;
    int n = h0;
    for (; n + 8 <= h1; n += 8, base += 8 * T4) {
        float4 v0 = Xp[base];
        float4 v1 = Xp[base + T4];
        float4 v2 = Xp[base + 2 * T4];
        float4 v3 = Xp[base + 3 * T4];
        float4 v4 = Xp[base + 4 * T4];
        float4 v5 = Xp[base + 5 * T4];
        float4 v6 = Xp[base + 6 * T4];
        float4 v7 = Xp[base + 7 * T4];
        ax += ((v0.x + v1.x) + (v2.x + v3.x)) + ((v4.x + v5.x) + (v6.x + v7.x));
        ay += ((v0.y + v1.y) + (v2.y + v3.y)) + ((v4.y + v5.y) + (v6.y + v7.y));
        az += ((v0.z + v1.z) + (v2.z + v3.z)) + ((v4.z + v5.z) + (v6.z + v7.z));
        aw += ((v0.w + v1.w) + (v2.w + v3.w)) + ((v4.w + v5.w) + (v6.w + v7.w));
    }
    for (; n + 4 <= h1; n += 4, base += 4 * T4) {
        float4 v0 = Xp[base];
        float4 v1 = Xp[base + T4];
        float4 v2 = Xp[base + 2 * T4];
        float4 v3 = Xp[base + 3 * T4];
        ax += (v0.x + v1.x) + (v2.x + v3.x);
        ay += (v0.y + v1.y) + (v2.y + v3.y);
        az += (v0.z + v1.z) + (v2.z + v3.z);
        aw += (v0.w + v1.w) + (v2.w + v3.w);
    }
    for (; n < h1; n++, base += T4) {
        float4 v = Xp[base];
        ax += v.x; ay += v.y; az += v.z; aw += v.w;
    }

    __shared__ float sacc[CB];
    if (threadIdx.x < CB) sacc[threadIdx.x] = 0.f;
    __syncthreads();

    int t = c4 * 4;
    int cb0 = col_ids[t];
    int cb3 = col_ids[t + 3];
    if (cb0 == cb3) {
        atomicAdd(&sacc[cb0], ax + ay + az + aw);
    } else {
        int cb1 = col_ids[t + 1];
        int cb2 = col_ids[t + 2];
        atomicAdd(&sacc[cb0], ax);
        atomicAdd(&sacc[cb1], ay);
        atomicAdd(&sacc[cb2], az);
        atomicAdd(&sacc[cb3], aw);
    }
    __syncthreads();
    if (threadIdx.x < CB)
        g_partial[rb][chunk * NSPLIT + half][threadIdx.x] = sacc[threadIdx.x];
}

// ---------------------------------------------------------------------------
// Kernel 3: fold partials -> block mean -> 1->3->3->1 relu MLP -> sigmoid.
// ---------------------------------------------------------------------------
__global__ void k_mlp(const float* __restrict__ W1, const float* __restrict__ b1,
                      const float* __restrict__ W2, const float* __restrict__ b2,
                      const float* __restrict__ W3, const float* __restrict__ b3,
                      float* __restrict__ out) {
    int idx = blockIdx.x * blockDim.x + threadIdx.x;
    if (idx >= RB * CB) return;
    int rb = idx / CB;
    int cb = idx % CB;
    float s = 0.f;
#pragma unroll
    for (int j = 0; j < NPART; j++) s += g_partial[rb][j][cb];
    float rcnt = (float)(g_row_start[rb + 1] - g_row_start[rb]);
    float ccnt = (float)(g_col_start[cb + 1] - g_col_start[cb]);
    float x = s / (rcnt * ccnt);

    float h1v[3], h2v[3];
#pragma unroll
    for (int j = 0; j < 3; j++) h1v[j] = fmaxf(x * W1[j] + b1[j], 0.f);
#pragma unroll
    for (int j = 0; j < 3; j++) {
        float v = b2[j];
#pragma unroll
        for (int i = 0; i < 3; i++) v += h1v[i] * W2[i * 3 + j];
        h2v[j] = fmaxf(v, 0.f);
    }
    float o = b3[0];
#pragma unroll
    for (int i = 0; i < 3; i++) o += h2v[i] * W3[i];
    out[idx] = 1.f / (1.f + __expf(-o));
}

extern "C" void kernel_launch(void* const* d_in, const int* in_sizes, int n_in,
                              void* d_out, int out_size) {
    const float* X       = (const float*)d_in[0];
    const int*   row_ids = (const int*)d_in[1];
    const int*   col_ids = (const int*)d_in[2];
    const float* W1      = (const float*)d_in[3];
    const float* b1      = (const float*)d_in[4];
    const float* W2      = (const float*)d_in[5];
    const float* b2      = (const float*)d_in[6];
    const float* W3      = (const float*)d_in[7];
    const float* b3      = (const float*)d_in[8];
    float* out = (float*)d_out;

    k_bounds<<<2, 1024>>>(row_ids, col_ids, out);
    k_sum<<<dim3(NCHUNK, RB, NSPLIT), 256>>>(X, col_ids);
    k_mlp<<<(RB * CB + 255) / 256, 256>>>(W1, b1, W2, b2, W3, b3, out);
}

// round 9
// speedup vs baseline: 1.3533x; 1.0154x over previous
#include <cuda_runtime.h>

#define RB 64
#define CB 64
#define NROWS 8192
#define TCOLS 8192
#define T4 (TCOLS / 4)         // 2048 float4 per row
#define NCHUNK 8               // 1024 columns (256 float4) per chunk
#define RANGE 64               // fixed rows per sum block
#define NRANGE (NROWS / RANGE) // 128

__device__ int   g_row_start[RB + 1];
__device__ int   g_col_start[CB + 1];
// zero at module load; k_mlp re-zeroes after reading so graph replays are clean
__device__ float g_sum[RB * CB];

// ---------------------------------------------------------------------------
// ONE main kernel. Grid (NCHUNK, NRANGE+1):
//   blockIdx.y == 0           -> bounds role (x=0: rows, x=1: cols; others idle)
//   blockIdx.y == 1..NRANGE   -> sum role for fixed row range (y-1)
// Sum blocks never read g_row_start (they read row_ids directly), so bounds
// and sums run concurrently; bounds cost hides under the 256 MB stream.
//
// Output layout:
//   out[0..4095]      propensity (written by k_mlp)
//   out[4096..4160]   row_cumsum (65, float values)
//   out[4161..4225]   col_cumsum (65, float values)
// ---------------------------------------------------------------------------
__global__ __launch_bounds__(256) void k_main(const float* __restrict__ X,
                                              const int* __restrict__ row_ids,
                                              const int* __restrict__ col_ids,
                                              float* __restrict__ out) {
    int tid = threadIdx.x;

    if (blockIdx.y == 0) {
        // -------- bounds role: sorted ids -> boundary detection --------
        if (blockIdx.x > 1) return;
        const int* __restrict__ ids = (blockIdx.x == 0) ? row_ids : col_ids;
        int* __restrict__ gstart = (blockIdx.x == 0) ? g_row_start : g_col_start;
        float* __restrict__ obase = out + RB * CB + blockIdx.x * 65;
        if (tid == 0) {
            gstart[0] = 0;       obase[0]  = 0.f;
            gstart[RB] = NROWS;  obase[RB] = (float)NROWS;
        }
        const int4* __restrict__ p = (const int4*)ids;
        for (int i = tid; i < NROWS / 4; i += 256) {
            int4 v = p[i];
            int j = 4 * i;
            if (j > 0) {
                int prev = ids[j - 1];
                if (v.x != prev) { gstart[v.x] = j;     obase[v.x] = (float)j; }
            }
            if (v.y != v.x) { gstart[v.y] = j + 1; obase[v.y] = (float)(j + 1); }
            if (v.z != v.y) { gstart[v.z] = j + 2; obase[v.z] = (float)(j + 2); }
            if (v.w != v.z) { gstart[v.w] = j + 3; obase[v.w] = (float)(j + 3); }
        }
        return;
    }

    // -------- sum role: fixed 64-row range x 1024-column chunk --------
    int f = blockIdx.y - 1;         // 0..NRANGE-1
    int chunk = blockIdx.x;         // 0..NCHUNK-1
    int R0 = f * RANGE;

    __shared__ int   srow[RANGE];
    __shared__ float sacc[CB];
    if (tid < RANGE) srow[tid] = row_ids[R0 + tid];

    int c4 = chunk * 256 + tid;                  // float4 column index
    int4 cbv = ((const int4*)col_ids)[c4];       // col block ids for 4 columns
    const float4* __restrict__ Xp = (const float4*)X;
    __syncthreads();

    int s = 0;
    while (s < RANGE) {
        int id = srow[s];
        // binary search (uniform across threads) for segment end
        int lo = s + 1, hi = RANGE;
        while (lo < hi) {
            int m = (lo + hi) >> 1;
            if (srow[m] == id) lo = m + 1; else hi = m;
        }
        int e = lo;                              // rows [s, e) share row-block id

        float ax = 0.f, ay = 0.f, az = 0.f, aw = 0.f;
        int n = s;
        int base = (R0 + s) * T4 + c4;
        for (; n + 4 <= e; n += 4, base += 4 * T4) {
            float4 v0 = Xp[base];
            float4 v1 = Xp[base + T4];
            float4 v2 = Xp[base + 2 * T4];
            float4 v3 = Xp[base + 3 * T4];
            ax += (v0.x + v1.x) + (v2.x + v3.x);
            ay += (v0.y + v1.y) + (v2.y + v3.y);
            az += (v0.z + v1.z) + (v2.z + v3.z);
            aw += (v0.w + v1.w) + (v2.w + v3.w);
        }
        for (; n < e; n++, base += T4) {
            float4 v = Xp[base];
            ax += v.x; ay += v.y; az += v.z; aw += v.w;
        }

        if (tid < CB) sacc[tid] = 0.f;
        __syncthreads();
        if (cbv.x == cbv.w) {
            atomicAdd(&sacc[cbv.x], ax + ay + az + aw);
        } else {
            atomicAdd(&sacc[cbv.x], ax);
            atomicAdd(&sacc[cbv.y], ay);
            atomicAdd(&sacc[cbv.z], az);
            atomicAdd(&sacc[cbv.w], aw);
        }
        __syncthreads();
        if (tid < CB) atomicAdd(&g_sum[id * CB + tid], sacc[tid]);
        __syncthreads();
        s = e;
    }
}

// ---------------------------------------------------------------------------
// Epilogue: block mean -> 1->3->3->1 relu MLP -> sigmoid. Re-zeroes g_sum
// after reading so the next graph replay starts clean.
// ---------------------------------------------------------------------------
__global__ void k_mlp(const float* __restrict__ W1, const float* __restrict__ b1,
                      const float* __restrict__ W2, const float* __restrict__ b2,
                      const float* __restrict__ W3, const float* __restrict__ b3,
                      float* __restrict__ out) {
    int idx = blockIdx.x * blockDim.x + threadIdx.x;
    if (idx >= RB * CB) return;
    int rb = idx / CB;
    int cb = idx % CB;
    float s = g_sum[idx];
    g_sum[idx] = 0.f;   // reset for next call
    float rcnt = (float)(g_row_start[rb + 1] - g_row_start[rb]);
    float ccnt = (float)(g_col_start[cb + 1] - g_col_start[cb]);
    float x = s / (rcnt * ccnt);

    float h1v[3], h2v[3];
#pragma unroll
    for (int j = 0; j < 3; j++) h1v[j] = fmaxf(x * W1[j] + b1[j], 0.f);
#pragma unroll
    for (int j = 0; j < 3; j++) {
        float v = b2[j];
#pragma unroll
        for (int i = 0; i < 3; i++) v += h1v[i] * W2[i * 3 + j];
        h2v[j] = fmaxf(v, 0.f);
    }
    float o = b3[0];
#pragma unroll
    for (int i = 0; i < 3; i++) o += h2v[i] * W3[i];
    out[idx] = 1.f / (1.f + __expf(-o));
}

extern "C" void kernel_launch(void* const* d_in, const int* in_sizes, int n_in,
                              void* d_out, int out_size) {
    const float* X       = (const float*)d_in[0];
    const int*   row_ids = (const int*)d_in[1];
    const int*   col_ids = (const int*)d_in[2];
    const float* W1      = (const float*)d_in[3];
    const float* b1      = (const float*)d_in[4];
    const float* W2      = (const float*)d_in[5];
    const float* b2      = (const float*)d_in[6];
    const float* W3      = (const float*)d_in[7];
    const float* b3      = (const float*)d_in[8];
    float* out = (float*)d_out;

    k_main<<<dim3(NCHUNK, NRANGE + 1), 256>>>(X, row_ids, col_ids, out);
    k_mlp<<<(RB * CB + 255) / 256, 256>>>(W1, b1, W2, b2, W3, b3, out);
}

// round 10
// speedup vs baseline: 1.4422x; 1.0657x over previous
#include <cuda_runtime.h>

#define RB 64
#define CB 64
#define NROWS 8192
#define TCOLS 8192
#define T4 (TCOLS / 4)         // 2048 float4 per row
#define NCHUNK 8               // 1024 columns (256 float4) per chunk
#define NSPLIT 2               // row halves per row-block

__device__ int   g_row_start[RB + 1];
__device__ int   g_col_start[CB + 1];
// zero at module load; k_mlp re-zeroes after reading so graph replays are clean
__device__ float g_sum[RB * CB];

// ---------------------------------------------------------------------------
// Kernel 1 (main): grid (NCHUNK+1, RB, NSPLIT).
//   chunk < NCHUNK  : sum role. Block finds its own row-block bounds via two
//                     binary searches on sorted row_ids (L2-hot, ~1.5us,
//                     overlapped), then streams its 1024-column chunk with
//                     the clean unroll-4 loop. Flushes via shared acc ->
//                     spread float atomics into g_sum.
//   chunk == NCHUNK : bounds-output role (rb==0: rows, rb==1: cols), writes
//                     cumsums to out and g_*_start for k_mlp. No sum block
//                     depends on it -> fully hidden under the stream.
//
// Output layout:
//   out[0..4095]      propensity (written by k_mlp)
//   out[4096..4160]   row_cumsum (65, float values)
//   out[4161..4225]   col_cumsum (65, float values)
// ---------------------------------------------------------------------------
__global__ __launch_bounds__(256) void k_sum(const float* __restrict__ X,
                                             const int* __restrict__ row_ids,
                                             const int* __restrict__ col_ids,
                                             float* __restrict__ out) {
    int tid = threadIdx.x;
    int chunk = blockIdx.x;            // 0..NCHUNK (last = bounds role)
    int rb    = blockIdx.y;            // 0..RB-1
    int half  = blockIdx.z;            // 0..NSPLIT-1

    if (chunk == NCHUNK) {
        // -------- bounds-output role --------
        if (rb > 1 || half != 0) return;
        const int* __restrict__ ids = (rb == 0) ? row_ids : col_ids;
        int* __restrict__ gstart = (rb == 0) ? g_row_start : g_col_start;
        float* __restrict__ obase = out + RB * CB + rb * 65;
        if (tid == 0) {
            gstart[0] = 0;       obase[0]  = 0.f;
            gstart[RB] = NROWS;  obase[RB] = (float)NROWS;
        }
        const int4* __restrict__ p = (const int4*)ids;
        for (int i = tid; i < NROWS / 4; i += 256) {
            int4 v = p[i];
            int j = 4 * i;
            if (j > 0) {
                int prev = ids[j - 1];
                if (v.x != prev) { gstart[v.x] = j;     obase[v.x] = (float)j; }
            }
            if (v.y != v.x) { gstart[v.y] = j + 1; obase[v.y] = (float)(j + 1); }
            if (v.z != v.y) { gstart[v.z] = j + 2; obase[v.z] = (float)(j + 2); }
            if (v.w != v.z) { gstart[v.w] = j + 3; obase[v.w] = (float)(j + 3); }
        }
        return;
    }

    // -------- sum role --------
    // lower_bound(row_ids, rb) and lower_bound(row_ids, rb+1), executed
    // uniformly by all threads (broadcast loads, cache-hot across blocks).
    int r0 = 0, r1;
    {
        int lo = 0, hi = NROWS;
        while (lo < hi) {
            int m = (lo + hi) >> 1;
            if (row_ids[m] < rb) lo = m + 1; else hi = m;
        }
        r0 = lo;
        lo = r0; hi = NROWS;
        while (lo < hi) {
            int m = (lo + hi) >> 1;
            if (row_ids[m] < rb + 1) lo = m + 1; else hi = m;
        }
        r1 = lo;
    }
    int len = r1 - r0;
    int h0 = r0 + (len * half) / NSPLIT;
    int h1 = r0 + (len * (half + 1)) / NSPLIT;

    int c4 = chunk * 256 + tid;                  // float4 column index
    const float4* __restrict__ Xp = (const float4*)X;

    float ax = 0.f, ay = 0.f, az = 0.f, aw = 0.f;
    int base = h0 * T4 + c4;
    int n = h0;
    for (; n + 4 <= h1; n += 4, base += 4 * T4) {
        float4 v0 = Xp[base];
        float4 v1 = Xp[base + T4];
        float4 v2 = Xp[base + 2 * T4];
        float4 v3 = Xp[base + 3 * T4];
        ax += (v0.x + v1.x) + (v2.x + v3.x);
        ay += (v0.y + v1.y) + (v2.y + v3.y);
        az += (v0.z + v1.z) + (v2.z + v3.z);
        aw += (v0.w + v1.w) + (v2.w + v3.w);
    }
    for (; n < h1; n++, base += T4) {
        float4 v = Xp[base];
        ax += v.x; ay += v.y; az += v.z; aw += v.w;
    }

    __shared__ float sacc[CB];
    if (tid < CB) sacc[tid] = 0.f;
    __syncthreads();

    int t = c4 * 4;
    int cb0 = col_ids[t];
    int cb3 = col_ids[t + 3];
    if (cb0 == cb3) {
        atomicAdd(&sacc[cb0], ax + ay + az + aw);
    } else {
        int cb1 = col_ids[t + 1];
        int cb2 = col_ids[t + 2];
        atomicAdd(&sacc[cb0], ax);
        atomicAdd(&sacc[cb1], ay);
        atomicAdd(&sacc[cb2], az);
        atomicAdd(&sacc[cb3], aw);
    }
    __syncthreads();
    if (tid < CB) atomicAdd(&g_sum[rb * CB + tid], sacc[tid]);
}

// ---------------------------------------------------------------------------
// Kernel 2: block mean -> 1->3->3->1 relu MLP -> sigmoid. Re-zeroes g_sum
// after reading so the next graph replay starts clean.
// ---------------------------------------------------------------------------
__global__ void k_mlp(const float* __restrict__ W1, const float* __restrict__ b1,
                      const float* __restrict__ W2, const float* __restrict__ b2,
                      const float* __restrict__ W3, const float* __restrict__ b3,
                      float* __restrict__ out) {
    int idx = blockIdx.x * blockDim.x + threadIdx.x;
    if (idx >= RB * CB) return;
    int rb = idx / CB;
    int cb = idx % CB;
    float s = g_sum[idx];
    g_sum[idx] = 0.f;   // reset for next call
    float rcnt = (float)(g_row_start[rb + 1] - g_row_start[rb]);
    float ccnt = (float)(g_col_start[cb + 1] - g_col_start[cb]);
    float x = s / (rcnt * ccnt);

    float h1v[3], h2v[3];
#pragma unroll
    for (int j = 0; j < 3; j++) h1v[j] = fmaxf(x * W1[j] + b1[j], 0.f);
#pragma unroll
    for (int j = 0; j < 3; j++) {
        float v = b2[j];
#pragma unroll
        for (int i = 0; i < 3; i++) v += h1v[i] * W2[i * 3 + j];
        h2v[j] = fmaxf(v, 0.f);
    }
    float o = b3[0];
#pragma unroll
    for (int i = 0; i < 3; i++) o += h2v[i] * W3[i];
    out[idx] = 1.f / (1.f + __expf(-o));
}

extern "C" void kernel_launch(void* const* d_in, const int* in_sizes, int n_in,
                              void* d_out, int out_size) {
    const float* X       = (const float*)d_in[0];
    const int*   row_ids = (const int*)d_in[1];
    const int*   col_ids = (const int*)d_in[2];
    const float* W1      = (const float*)d_in[3];
    const float* b1      = (const float*)d_in[4];
    const float* W2      = (const float*)d_in[5];
    const float* b2      = (const float*)d_in[6];
    const float* W3      = (const float*)d_in[7];
    const float* b3      = (const float*)d_in[8];
    float* out = (float*)d_out;

    k_sum<<<dim3(NCHUNK + 1, RB, NSPLIT), 256>>>(X, row_ids, col_ids, out);
    k_mlp<<<(RB * CB + 255) / 256, 256>>>(W1, b1, W2, b2, W3, b3, out);
}